// round 1
// baseline (speedup 1.0000x reference)
#include <cuda_runtime.h>
#include <cuda_bf16.h>

// Problem constants
#define BB 4
#define SS 4096
#define HID 1024
#define HEADS 8
#define DD 128
#define NSEG 16
#define SEGLEN 256
#define EE_N 16
#define II 512
#define NGROUP (BB * NSEG * HEADS)   // 512
#define MROWS (BB * SS)              // 16384

// Scratch (device globals — allocation-free per harness rules)
__device__ float g_xh[MROWS * HID];                  // after W_mh:  64 MB
__device__ float g_ew[NGROUP * EE_N];                // routing weights
__device__ float g_m1[NGROUP * II * DD];             // mixed first_linear: 134 MB
__device__ float g_m2[NGROUP * DD * II];             // mixed second_linear: 134 MB
__device__ float g_h[NGROUP * SEGLEN * II];          // hidden: 268 MB
__device__ float g_y2[MROWS * HID];                  // pre-merge: 64 MB

// ---------------------------------------------------------------------------
// Generic batched SGEMM:  C[g] = A[g] (M x K, row stride lda)
//                                 * B[g]^T (B is N x K row-major, ld = K)
//                                 (+ bias[n]) (optional relu)
// Batch offsets are linear: ptr += g * batchStride.
// Requires M%128==0, N%128==0, K%8==0 (true for all call sites here).
// ---------------------------------------------------------------------------
#define BM 128
#define BN 128
#define BKK 8
#define TM 8
#define TN 8

__global__ __launch_bounds__(256, 2)
void sgemm_bt(const float* __restrict__ A, const float* __restrict__ B,
              float* __restrict__ C, const float* __restrict__ bias,
              int M, int N, int K, int lda, int ldc,
              long long aBatch, long long bBatch, long long cBatch,
              int doRelu)
{
    __shared__ float As[BKK][BM];
    __shared__ float Bs[BKK][BN];

    long long g = blockIdx.z;
    A += g * aBatch;
    B += g * bBatch;
    C += g * cBatch;

    const int bm = blockIdx.y * BM;
    const int bn = blockIdx.x * BN;
    const int t  = threadIdx.x;

    // Loading indices: each thread loads one float4 of A and one of B per k-step
    const int ldRow = t >> 1;          // 0..127
    const int ldK   = (t & 1) * 4;     // 0 or 4

    const float* Aptr = A + (long long)(bm + ldRow) * lda + ldK;
    const float* Bptr = B + (long long)(bn + ldRow) * K   + ldK;

    const int tr = (t >> 4) * TM;      // 0,8,...,120
    const int tc = (t & 15) * TN;      // 0,8,...,120

    float acc[TM][TN];
#pragma unroll
    for (int i = 0; i < TM; i++)
#pragma unroll
        for (int j = 0; j < TN; j++) acc[i][j] = 0.f;

    float ra[TM], rb[TN];

    for (int k0 = 0; k0 < K; k0 += BKK) {
        float4 av = *reinterpret_cast<const float4*>(Aptr);
        float4 bv = *reinterpret_cast<const float4*>(Bptr);
        As[ldK + 0][ldRow] = av.x;
        As[ldK + 1][ldRow] = av.y;
        As[ldK + 2][ldRow] = av.z;
        As[ldK + 3][ldRow] = av.w;
        Bs[ldK + 0][ldRow] = bv.x;
        Bs[ldK + 1][ldRow] = bv.y;
        Bs[ldK + 2][ldRow] = bv.z;
        Bs[ldK + 3][ldRow] = bv.w;
        __syncthreads();

#pragma unroll
        for (int k = 0; k < BKK; k++) {
            *reinterpret_cast<float4*>(&ra[0]) = *reinterpret_cast<const float4*>(&As[k][tr]);
            *reinterpret_cast<float4*>(&ra[4]) = *reinterpret_cast<const float4*>(&As[k][tr + 4]);
            *reinterpret_cast<float4*>(&rb[0]) = *reinterpret_cast<const float4*>(&Bs[k][tc]);
            *reinterpret_cast<float4*>(&rb[4]) = *reinterpret_cast<const float4*>(&Bs[k][tc + 4]);
#pragma unroll
            for (int i = 0; i < TM; i++)
#pragma unroll
                for (int j = 0; j < TN; j++)
                    acc[i][j] = fmaf(ra[i], rb[j], acc[i][j]);
        }
        __syncthreads();
        Aptr += BKK;
        Bptr += BKK;
    }

    // Epilogue
    float bset[TN];
#pragma unroll
    for (int j = 0; j < TN; j++)
        bset[j] = bias ? bias[bn + tc + j] : 0.f;

#pragma unroll
    for (int i = 0; i < TM; i++) {
        const long long crow = (long long)(bm + tr + i) * ldc + bn + tc;
        float v[TN];
#pragma unroll
        for (int j = 0; j < TN; j++) {
            float x = acc[i][j] + bset[j];
            v[j] = doRelu ? fmaxf(x, 0.f) : x;
        }
        *reinterpret_cast<float4*>(&C[crow])     = make_float4(v[0], v[1], v[2], v[3]);
        *reinterpret_cast<float4*>(&C[crow + 4]) = make_float4(v[4], v[5], v[6], v[7]);
    }
}

// ---------------------------------------------------------------------------
// Segment mean over SEGLEN + routing logits + softmax -> ew[g][e]
// grid: 512 blocks (one per (b,n,h) with ORIGINAL head grouping), 128 threads
// ---------------------------------------------------------------------------
__global__ void avg_softmax_kernel(const float* __restrict__ xh,
                                   const float* __restrict__ embed,   // [D, E]
                                   float* __restrict__ ew)
{
    __shared__ float avg_s[DD];
    __shared__ float lg[EE_N];

    const int g = blockIdx.x;          // (b*16+n)*8 + h
    const int d = threadIdx.x;
    const int b = g >> 7;
    const int n = (g >> 3) & 15;
    const int h = g & 7;

    const float* p = xh + (long long)(b * SS + n * SEGLEN) * HID + h * DD + d;
    float s = 0.f;
#pragma unroll 8
    for (int l = 0; l < SEGLEN; l++) s += p[(long long)l * HID];
    avg_s[d] = s * (1.f / (float)SEGLEN);
    __syncthreads();

    if (d < EE_N) {
        float a = 0.f;
        for (int dd = 0; dd < DD; dd++) a += avg_s[dd] * embed[dd * EE_N + d];
        lg[d] = a;
    }
    __syncthreads();

    if (d == 0) {
        float mx = lg[0];
        for (int e = 1; e < EE_N; e++) mx = fmaxf(mx, lg[e]);
        float ex[EE_N];
        float ssum = 0.f;
        for (int e = 0; e < EE_N; e++) { ex[e] = expf(lg[e] - mx); ssum += ex[e]; }
        float inv = 1.f / ssum;
        for (int e = 0; e < EE_N; e++) ew[g * EE_N + e] = ex[e] * inv;
    }
}

// ---------------------------------------------------------------------------
// Expert mixing with causal shift:
//   m{1,2}[g] = sum_e ew[g_shifted][e] * linear[e]
// where g=(b,n,h) uses weights of segment max(n-1,0)  (g' = n>0 ? g-8 : g).
// grid (512, 2): x = 128-wide slab of the 65536 (i,d)/(d,i) positions,
//                y = which matrix (0 -> first_linear/m1, 1 -> second_linear/m2)
// ---------------------------------------------------------------------------
__global__ void mix_kernel(const float* __restrict__ ew,
                           const float* __restrict__ fl1,
                           const float* __restrict__ fl2,
                           float* __restrict__ m1,
                           float* __restrict__ m2)
{
    __shared__ float w_s[NGROUP * EE_N];   // 32 KB, causally shifted weights

    const int t = threadIdx.x;             // 128 threads
    const float* src = blockIdx.y ? fl2 : fl1;
    float*       dst = blockIdx.y ? m2  : m1;
    const long long p = (long long)blockIdx.x * 128 + t;   // 0..65535

    for (int idx = t; idx < NGROUP * EE_N; idx += 128) {
        int g  = idx >> 4;
        int n  = (g >> 3) & 15;
        int gs = (n > 0) ? (g - HEADS) : g;
        w_s[idx] = ew[gs * EE_N + (idx & 15)];
    }

    float flr[EE_N];
#pragma unroll
    for (int e = 0; e < EE_N; e++) flr[e] = src[(long long)e * (II * DD) + p];
    __syncthreads();

    for (int g = 0; g < NGROUP; g++) {
        float acc = 0.f;
#pragma unroll
        for (int e = 0; e < EE_N; e++) acc = fmaf(w_s[g * EE_N + e], flr[e], acc);
        dst[(long long)g * (II * DD) + p] = acc;
    }
}

// ---------------------------------------------------------------------------
// Launch
// ---------------------------------------------------------------------------
extern "C" void kernel_launch(void* const* d_in, const int* in_sizes, int n_in,
                              void* d_out, int out_size)
{
    const float* x       = (const float*)d_in[0];
    const float* W_mh    = (const float*)d_in[1];
    const float* b_mh    = (const float*)d_in[2];
    const float* W_merge = (const float*)d_in[3];
    const float* b_merge = (const float*)d_in[4];
    const float* embed   = (const float*)d_in[5];
    const float* fl1     = (const float*)d_in[6];
    const float* fl2     = (const float*)d_in[7];
    float* out = (float*)d_out;

    float *xh, *ew, *m1, *m2, *hb, *y2;
    cudaGetSymbolAddress((void**)&xh, g_xh);
    cudaGetSymbolAddress((void**)&ew, g_ew);
    cudaGetSymbolAddress((void**)&m1, g_m1);
    cudaGetSymbolAddress((void**)&m2, g_m2);
    cudaGetSymbolAddress((void**)&hb, g_h);
    cudaGetSymbolAddress((void**)&y2, g_y2);

    // 1) xh = x @ W_mh^T + b_mh          [16384,1024] x [1024,1024]
    sgemm_bt<<<dim3(HID / BN, MROWS / BM, 1), 256>>>(
        x, W_mh, xh, b_mh, MROWS, HID, HID, HID, HID, 0, 0, 0, 0);

    // 2) segment-mean + routing softmax -> ew[512][16]
    avg_softmax_kernel<<<NGROUP, DD>>>(xh, embed, ew);

    // 3) causally-shifted expert mixing -> m1[512][512*128], m2[512][128*512]
    mix_kernel<<<dim3(II * DD / 128, 2), 128>>>(ew, fl1, fl2, m1, m2);

    // 4) h = relu(X @ m1^T)  batched over 512 groups: M=256, N=512, K=128
    //    X group tile is contiguous [256,128] at stride 32768 in xh
    sgemm_bt<<<dim3(II / BN, SEGLEN / BM, NGROUP), 256>>>(
        xh, m1, hb, nullptr, SEGLEN, II, DD, DD, II,
        (long long)SEGLEN * DD, (long long)II * DD, (long long)SEGLEN * II, 1);

    // 5) y2 = h @ m2^T       batched: M=256, N=128, K=512
    sgemm_bt<<<dim3(DD / BN, SEGLEN / BM, NGROUP), 256>>>(
        hb, m2, y2, nullptr, SEGLEN, DD, II, II, DD,
        (long long)SEGLEN * II, (long long)DD * II, (long long)SEGLEN * DD, 0);

    // 6) out = y2 @ W_merge^T + b_merge
    sgemm_bt<<<dim3(HID / BN, MROWS / BM, 1), 256>>>(
        y2, W_merge, out, b_merge, MROWS, HID, HID, HID, HID, 0, 0, 0, 0);
}

// round 2
// speedup vs baseline: 1.0008x; 1.0008x over previous
#include <cuda_runtime.h>
#include <cuda_bf16.h>

// Problem constants
#define BB 4
#define SS 4096
#define HID 1024
#define HEADS 8
#define DD 128
#define NSEG 16
#define SEGLEN 256
#define EE_N 16
#define II 512
#define NGROUP (BB * NSEG * HEADS)   // 512
#define MROWS (BB * SS)              // 16384

// Scratch (device globals — allocation-free per harness rules)
__device__ float g_xh[MROWS * HID];                  // after W_mh:  64 MB
__device__ float g_ew[NGROUP * EE_N];                // routing weights
__device__ float g_m1[NGROUP * II * DD];             // mixed first_linear: 134 MB
__device__ float g_m2[NGROUP * DD * II];             // mixed second_linear: 134 MB
__device__ float g_h[NGROUP * SEGLEN * II];          // hidden: 268 MB
__device__ float g_y2[MROWS * HID];                  // pre-merge: 64 MB

// ---------------------------------------------------------------------------
// Generic batched SGEMM:  C[g] = A[g] (M x K, row stride lda)
//                                 * B[g]^T (B is N x K row-major, ld = K)
//                                 (+ bias[n]) (optional relu)
// Batch offsets are linear: ptr += g * batchStride.
// Requires M%128==0, N%128==0, K%8==0 (true for all call sites here).
// ---------------------------------------------------------------------------
#define BM 128
#define BN 128
#define BKK 8
#define TM 8
#define TN 8

__global__ __launch_bounds__(256, 2)
void sgemm_bt(const float* __restrict__ A, const float* __restrict__ B,
              float* __restrict__ C, const float* __restrict__ bias,
              int M, int N, int K, int lda, int ldc,
              long long aBatch, long long bBatch, long long cBatch,
              int doRelu)
{
    __shared__ float As[BKK][BM];
    __shared__ float Bs[BKK][BN];

    long long g = blockIdx.z;
    A += g * aBatch;
    B += g * bBatch;
    C += g * cBatch;

    const int bm = blockIdx.y * BM;
    const int bn = blockIdx.x * BN;
    const int t  = threadIdx.x;

    // Loading indices: each thread loads one float4 of A and one of B per k-step
    const int ldRow = t >> 1;          // 0..127
    const int ldK   = (t & 1) * 4;     // 0 or 4

    const float* Aptr = A + (long long)(bm + ldRow) * lda + ldK;
    const float* Bptr = B + (long long)(bn + ldRow) * K   + ldK;

    const int tr = (t >> 4) * TM;      // 0,8,...,120
    const int tc = (t & 15) * TN;      // 0,8,...,120

    float acc[TM][TN];
#pragma unroll
    for (int i = 0; i < TM; i++)
#pragma unroll
        for (int j = 0; j < TN; j++) acc[i][j] = 0.f;

    float ra[TM], rb[TN];

    for (int k0 = 0; k0 < K; k0 += BKK) {
        float4 av = *reinterpret_cast<const float4*>(Aptr);
        float4 bv = *reinterpret_cast<const float4*>(Bptr);
        As[ldK + 0][ldRow] = av.x;
        As[ldK + 1][ldRow] = av.y;
        As[ldK + 2][ldRow] = av.z;
        As[ldK + 3][ldRow] = av.w;
        Bs[ldK + 0][ldRow] = bv.x;
        Bs[ldK + 1][ldRow] = bv.y;
        Bs[ldK + 2][ldRow] = bv.z;
        Bs[ldK + 3][ldRow] = bv.w;
        __syncthreads();

#pragma unroll
        for (int k = 0; k < BKK; k++) {
            *reinterpret_cast<float4*>(&ra[0]) = *reinterpret_cast<const float4*>(&As[k][tr]);
            *reinterpret_cast<float4*>(&ra[4]) = *reinterpret_cast<const float4*>(&As[k][tr + 4]);
            *reinterpret_cast<float4*>(&rb[0]) = *reinterpret_cast<const float4*>(&Bs[k][tc]);
            *reinterpret_cast<float4*>(&rb[4]) = *reinterpret_cast<const float4*>(&Bs[k][tc + 4]);
#pragma unroll
            for (int i = 0; i < TM; i++)
#pragma unroll
                for (int j = 0; j < TN; j++)
                    acc[i][j] = fmaf(ra[i], rb[j], acc[i][j]);
        }
        __syncthreads();
        Aptr += BKK;
        Bptr += BKK;
    }

    // Epilogue
    float bset[TN];
#pragma unroll
    for (int j = 0; j < TN; j++)
        bset[j] = bias ? bias[bn + tc + j] : 0.f;

#pragma unroll
    for (int i = 0; i < TM; i++) {
        const long long crow = (long long)(bm + tr + i) * ldc + bn + tc;
        float v[TN];
#pragma unroll
        for (int j = 0; j < TN; j++) {
            float x = acc[i][j] + bset[j];
            v[j] = doRelu ? fmaxf(x, 0.f) : x;
        }
        *reinterpret_cast<float4*>(&C[crow])     = make_float4(v[0], v[1], v[2], v[3]);
        *reinterpret_cast<float4*>(&C[crow + 4]) = make_float4(v[4], v[5], v[6], v[7]);
    }
}

// ---------------------------------------------------------------------------
// Segment mean over SEGLEN + routing logits + softmax -> ew[g][e]
// grid: 512 blocks (one per (b,n,h) with ORIGINAL head grouping), 128 threads
// ---------------------------------------------------------------------------
__global__ void avg_softmax_kernel(const float* __restrict__ xh,
                                   const float* __restrict__ embed,   // [D, E]
                                   float* __restrict__ ew)
{
    __shared__ float avg_s[DD];
    __shared__ float lg[EE_N];

    const int g = blockIdx.x;          // (b*16+n)*8 + h
    const int d = threadIdx.x;
    const int b = g >> 7;
    const int n = (g >> 3) & 15;
    const int h = g & 7;

    const float* p = xh + (long long)(b * SS + n * SEGLEN) * HID + h * DD + d;
    float s = 0.f;
#pragma unroll 8
    for (int l = 0; l < SEGLEN; l++) s += p[(long long)l * HID];
    avg_s[d] = s * (1.f / (float)SEGLEN);
    __syncthreads();

    if (d < EE_N) {
        float a = 0.f;
        for (int dd = 0; dd < DD; dd++) a += avg_s[dd] * embed[dd * EE_N + d];
        lg[d] = a;
    }
    __syncthreads();

    if (d == 0) {
        float mx = lg[0];
        for (int e = 1; e < EE_N; e++) mx = fmaxf(mx, lg[e]);
        float ex[EE_N];
        float ssum = 0.f;
        for (int e = 0; e < EE_N; e++) { ex[e] = expf(lg[e] - mx); ssum += ex[e]; }
        float inv = 1.f / ssum;
        for (int e = 0; e < EE_N; e++) ew[g * EE_N + e] = ex[e] * inv;
    }
}

// ---------------------------------------------------------------------------
// Expert mixing with causal shift:
//   m{1,2}[g] = sum_e ew[g_shifted][e] * linear[e]
// where g=(b,n,h) uses weights of segment max(n-1,0)  (g' = n>0 ? g-8 : g).
// grid (512, 2): x = 128-wide slab of the 65536 (i,d)/(d,i) positions,
//                y = which matrix (0 -> first_linear/m1, 1 -> second_linear/m2)
// ---------------------------------------------------------------------------
__global__ void mix_kernel(const float* __restrict__ ew,
                           const float* __restrict__ fl1,
                           const float* __restrict__ fl2,
                           float* __restrict__ m1,
                           float* __restrict__ m2)
{
    __shared__ float w_s[NGROUP * EE_N];   // 32 KB, causally shifted weights

    const int t = threadIdx.x;             // 128 threads
    const float* src = blockIdx.y ? fl2 : fl1;
    float*       dst = blockIdx.y ? m2  : m1;
    const long long p = (long long)blockIdx.x * 128 + t;   // 0..65535

    for (int idx = t; idx < NGROUP * EE_N; idx += 128) {
        int g  = idx >> 4;
        int n  = (g >> 3) & 15;
        int gs = (n > 0) ? (g - HEADS) : g;
        w_s[idx] = ew[gs * EE_N + (idx & 15)];
    }

    float flr[EE_N];
#pragma unroll
    for (int e = 0; e < EE_N; e++) flr[e] = src[(long long)e * (II * DD) + p];
    __syncthreads();

    for (int g = 0; g < NGROUP; g++) {
        float acc = 0.f;
#pragma unroll
        for (int e = 0; e < EE_N; e++) acc = fmaf(w_s[g * EE_N + e], flr[e], acc);
        dst[(long long)g * (II * DD) + p] = acc;
    }
}

// ---------------------------------------------------------------------------
// Launch
// ---------------------------------------------------------------------------
extern "C" void kernel_launch(void* const* d_in, const int* in_sizes, int n_in,
                              void* d_out, int out_size)
{
    const float* x       = (const float*)d_in[0];
    const float* W_mh    = (const float*)d_in[1];
    const float* b_mh    = (const float*)d_in[2];
    const float* W_merge = (const float*)d_in[3];
    const float* b_merge = (const float*)d_in[4];
    const float* embed   = (const float*)d_in[5];
    const float* fl1     = (const float*)d_in[6];
    const float* fl2     = (const float*)d_in[7];
    float* out = (float*)d_out;

    float *xh, *ew, *m1, *m2, *hb, *y2;
    cudaGetSymbolAddress((void**)&xh, g_xh);
    cudaGetSymbolAddress((void**)&ew, g_ew);
    cudaGetSymbolAddress((void**)&m1, g_m1);
    cudaGetSymbolAddress((void**)&m2, g_m2);
    cudaGetSymbolAddress((void**)&hb, g_h);
    cudaGetSymbolAddress((void**)&y2, g_y2);

    // 1) xh = x @ W_mh^T + b_mh          [16384,1024] x [1024,1024]
    sgemm_bt<<<dim3(HID / BN, MROWS / BM, 1), 256>>>(
        x, W_mh, xh, b_mh, MROWS, HID, HID, HID, HID, 0, 0, 0, 0);

    // 2) segment-mean + routing softmax -> ew[512][16]
    avg_softmax_kernel<<<NGROUP, DD>>>(xh, embed, ew);

    // 3) causally-shifted expert mixing -> m1[512][512*128], m2[512][128*512]
    mix_kernel<<<dim3(II * DD / 128, 2), 128>>>(ew, fl1, fl2, m1, m2);

    // 4) h = relu(X @ m1^T)  batched over 512 groups: M=256, N=512, K=128
    //    X group tile is contiguous [256,128] at stride 32768 in xh
    sgemm_bt<<<dim3(II / BN, SEGLEN / BM, NGROUP), 256>>>(
        xh, m1, hb, nullptr, SEGLEN, II, DD, DD, II,
        (long long)SEGLEN * DD, (long long)II * DD, (long long)SEGLEN * II, 1);

    // 5) y2 = h @ m2^T       batched: M=256, N=128, K=512
    sgemm_bt<<<dim3(DD / BN, SEGLEN / BM, NGROUP), 256>>>(
        hb, m2, y2, nullptr, SEGLEN, DD, II, II, DD,
        (long long)SEGLEN * II, (long long)DD * II, (long long)SEGLEN * DD, 0);

    // 6) out = y2 @ W_merge^T + b_merge
    sgemm_bt<<<dim3(HID / BN, MROWS / BM, 1), 256>>>(
        y2, W_merge, out, b_merge, MROWS, HID, HID, HID, HID, 0, 0, 0, 0);
}

// round 4
// speedup vs baseline: 2.4381x; 2.4363x over previous
#include <cuda_runtime.h>
#include <cuda_bf16.h>
#include <cstdint>

#define HID 1024
#define HEADS 8
#define DD 128
#define NSEG 16
#define SEGLEN 256
#define EE_N 16
#define II 512
#define NGROUP 512
#define MROWS 16384
#define SS_ 4096

__device__ __nv_bfloat16 g_xb_hi[MROWS * HID];
__device__ __nv_bfloat16 g_xb_lo[MROWS * HID];
__device__ __nv_bfloat16 g_wmh_hi[HID * HID];
__device__ __nv_bfloat16 g_wmh_lo[HID * HID];
__device__ __nv_bfloat16 g_wmg_hi[HID * HID];
__device__ __nv_bfloat16 g_wmg_lo[HID * HID];
__device__ __nv_bfloat16 g_xh_hi[MROWS * HID];
__device__ __nv_bfloat16 g_xh_lo[MROWS * HID];
__device__ float         g_ew[NGROUP * EE_N];
__device__ __nv_bfloat16 g_m1_hi[NGROUP * II * DD];
__device__ __nv_bfloat16 g_m1_lo[NGROUP * II * DD];
__device__ __nv_bfloat16 g_m2_hi[NGROUP * DD * II];
__device__ __nv_bfloat16 g_m2_lo[NGROUP * DD * II];
__device__ __nv_bfloat16 g_h_hi[NGROUP * SEGLEN * II];
__device__ __nv_bfloat16 g_h_lo[NGROUP * SEGLEN * II];
__device__ __nv_bfloat16 g_y2_hi[MROWS * HID];
__device__ __nv_bfloat16 g_y2_lo[MROWS * HID];

__device__ __forceinline__ uint32_t smem_u32(const void* p) {
    uint32_t a;
    asm("{ .reg .u64 t; cvta.to.shared.u64 t, %1; cvt.u32.u64 %0, t; }" : "=r"(a) : "l"(p));
    return a;
}
__device__ __forceinline__ void cp_async16(uint32_t dst, const void* src) {
    asm volatile("cp.async.cg.shared.global [%0], [%1], 16;" :: "r"(dst), "l"(src) : "memory");
}

#define LDSM4(r, ad) \
    asm volatile("ldmatrix.sync.aligned.m8n8.x4.shared.b16 {%0,%1,%2,%3}, [%4];" \
        : "=r"((r)[0]), "=r"((r)[1]), "=r"((r)[2]), "=r"((r)[3]) : "r"(ad))

#define MMA(c, a, b) \
    asm volatile("mma.sync.aligned.m16n8k16.row.col.f32.bf16.bf16.f32 " \
        "{%0,%1,%2,%3},{%4,%5,%6,%7},{%8,%9},{%0,%1,%2,%3};" \
        : "+f"((c)[0]), "+f"((c)[1]), "+f"((c)[2]), "+f"((c)[3]) \
        : "r"((a)[0]), "r"((a)[1]), "r"((a)[2]), "r"((a)[3]), "r"((b)[0]), "r"((b)[1]))

// smem: 4 planes (Ah,Al,Bh,Bl), 128 rows x 64B, pitch 80B; double buffered
#define RPITCH 80
#define PLANE  (128 * RPITCH)     // 10240
#define STAGE  (4 * PLANE)        // 40960
#define SMEM_BYTES (2 * STAGE)    // 81920

// C[128,128] += A * B^T over K (bf16 hi/lo planes, fp32 accum, 3 products)
// Out: bf16 hi/lo planes (bias/relu) or fp32 (+bias). K % 32 == 0.
__global__ __launch_bounds__(256)
void mma_gemm(const __nv_bfloat16* __restrict__ Ahi, const __nv_bfloat16* __restrict__ Alo,
              const __nv_bfloat16* __restrict__ Bhi, const __nv_bfloat16* __restrict__ Blo,
              __nv_bfloat16* __restrict__ Chi, __nv_bfloat16* __restrict__ Clo,
              float* __restrict__ Cf, const float* __restrict__ bias,
              int K, int lda, int ldb, int ldc,
              long long aB, long long bB, long long cB, int doRelu)
{
    extern __shared__ char dsm[];
    const int tid  = threadIdx.x;
    const int lane = tid & 31;
    const int warp = tid >> 5;
    const int wm   = warp & 1;     // 0..1 : 64-row slab
    const int wn   = warp >> 1;    // 0..3 : 32-col slab

    const long long gz = blockIdx.z;
    Ahi += gz * aB;  Alo += gz * aB;
    Bhi += gz * bB;  Blo += gz * bB;
    const long long coff = gz * cB;
    const int m0 = blockIdx.y * 128;
    const int n0 = blockIdx.x * 128;

    const uint32_t sb = smem_u32(dsm);
    const int NK = K >> 5;

    float acc[4][4][4];
#pragma unroll
    for (int i = 0; i < 4; i++)
#pragma unroll
        for (int j = 0; j < 4; j++)
#pragma unroll
            for (int q = 0; q < 4; q++) acc[i][j][q] = 0.f;

#define ISSUE(kt)                                                              \
    {                                                                          \
        const int k0_ = (kt) << 5;                                             \
        const uint32_t db_ = sb + ((kt) & 1) * STAGE;                          \
        _Pragma("unroll")                                                      \
        for (int it = 0; it < 8; it++) {                                       \
            int idx = it * 256 + tid;                                          \
            int pl = idx >> 9;                                                 \
            int r  = (idx >> 2) & 127;                                         \
            int ch = idx & 3;                                                  \
            const __nv_bfloat16* sp;                                           \
            if (pl == 0)      sp = Ahi + (long long)(m0 + r) * lda + k0_ + ch * 8; \
            else if (pl == 1) sp = Alo + (long long)(m0 + r) * lda + k0_ + ch * 8; \
            else if (pl == 2) sp = Bhi + (long long)(n0 + r) * ldb + k0_ + ch * 8; \
            else              sp = Blo + (long long)(n0 + r) * ldb + k0_ + ch * 8; \
            cp_async16(db_ + pl * PLANE + r * RPITCH + ch * 16, sp);           \
        }                                                                      \
        asm volatile("cp.async.commit_group;" ::: "memory");                   \
    }

    // per-lane ldmatrix offsets
    const int rowOffA = (lane & 7) + ((lane >> 3) & 1) * 8;
    const int kOffA   = ((lane >> 4) & 1) * 8;
    const int rowOffB = (lane & 7) + ((lane >> 4) & 1) * 8;
    const int kOffB   = ((lane >> 3) & 1) * 8;

    ISSUE(0);
    for (int kt = 0; kt < NK; kt++) {
        if (kt + 1 < NK) {
            ISSUE(kt + 1);
            asm volatile("cp.async.wait_group 1;" ::: "memory");
        } else {
            asm volatile("cp.async.wait_group 0;" ::: "memory");
        }
        __syncthreads();

        const uint32_t base = sb + (kt & 1) * STAGE;
#pragma unroll
        for (int ks = 0; ks < 2; ks++) {
            uint32_t a_h[4][4], a_l[4][4], b_h[4][2], b_l[4][2];
#pragma unroll
            for (int mt = 0; mt < 4; mt++) {
                uint32_t ad = base + (wm * 64 + mt * 16 + rowOffA) * RPITCH
                            + (ks * 16 + kOffA) * 2;
                LDSM4(a_h[mt], ad);
                LDSM4(a_l[mt], ad + PLANE);
            }
#pragma unroll
            for (int pr = 0; pr < 2; pr++) {
                uint32_t bd = base + 2 * PLANE
                            + (wn * 32 + pr * 16 + rowOffB) * RPITCH
                            + (ks * 16 + kOffB) * 2;
                uint32_t r4[4];
                LDSM4(r4, bd);
                b_h[pr * 2][0] = r4[0]; b_h[pr * 2][1] = r4[1];
                b_h[pr * 2 + 1][0] = r4[2]; b_h[pr * 2 + 1][1] = r4[3];
                LDSM4(r4, bd + PLANE);
                b_l[pr * 2][0] = r4[0]; b_l[pr * 2][1] = r4[1];
                b_l[pr * 2 + 1][0] = r4[2]; b_l[pr * 2 + 1][1] = r4[3];
            }
#pragma unroll
            for (int mt = 0; mt < 4; mt++)
#pragma unroll
                for (int nt = 0; nt < 4; nt++) {
                    MMA(acc[mt][nt], a_h[mt], b_h[nt]);
                    MMA(acc[mt][nt], a_h[mt], b_l[nt]);
                    MMA(acc[mt][nt], a_l[mt], b_h[nt]);
                }
        }
        __syncthreads();
    }

    // epilogue
    const int rq = lane >> 2;
    const int cq = (lane & 3) * 2;
#pragma unroll
    for (int mt = 0; mt < 4; mt++)
#pragma unroll
        for (int nt = 0; nt < 4; nt++) {
            const int row = m0 + wm * 64 + mt * 16 + rq;
            const int col = n0 + wn * 32 + nt * 8 + cq;
            float b0 = bias ? bias[col] : 0.f;
            float b1 = bias ? bias[col + 1] : 0.f;
#pragma unroll
            for (int half = 0; half < 2; half++) {
                const long long rr = (long long)(row + half * 8) * ldc + col + coff;
                float v0 = acc[mt][nt][half * 2 + 0] + b0;
                float v1 = acc[mt][nt][half * 2 + 1] + b1;
                if (doRelu) { v0 = fmaxf(v0, 0.f); v1 = fmaxf(v1, 0.f); }
                if (Cf) {
                    *reinterpret_cast<float2*>(Cf + rr) = make_float2(v0, v1);
                } else {
                    __nv_bfloat16 h0 = __float2bfloat16(v0);
                    __nv_bfloat16 h1 = __float2bfloat16(v1);
                    __nv_bfloat162 hp; hp.x = h0; hp.y = h1;
                    __nv_bfloat162 lp;
                    lp.x = __float2bfloat16(v0 - __bfloat162float(h0));
                    lp.y = __float2bfloat16(v1 - __bfloat162float(h1));
                    *reinterpret_cast<__nv_bfloat162*>(Chi + rr) = hp;
                    *reinterpret_cast<__nv_bfloat162*>(Clo + rr) = lp;
                }
            }
        }
}

__global__ void split_kernel(const float4* __restrict__ in,
                             __nv_bfloat16* __restrict__ hi,
                             __nv_bfloat16* __restrict__ lo, int n4)
{
    for (long long i = blockIdx.x * blockDim.x + threadIdx.x; i < n4;
         i += (long long)gridDim.x * blockDim.x) {
        float4 v = in[i];
        __nv_bfloat162 a, b, c, d;
        a.x = __float2bfloat16(v.x); a.y = __float2bfloat16(v.y);
        b.x = __float2bfloat16(v.z); b.y = __float2bfloat16(v.w);
        c.x = __float2bfloat16(v.x - __bfloat162float(a.x));
        c.y = __float2bfloat16(v.y - __bfloat162float(a.y));
        d.x = __float2bfloat16(v.z - __bfloat162float(b.x));
        d.y = __float2bfloat16(v.w - __bfloat162float(b.y));
        reinterpret_cast<__nv_bfloat162*>(hi)[2 * i]     = a;
        reinterpret_cast<__nv_bfloat162*>(hi)[2 * i + 1] = b;
        reinterpret_cast<__nv_bfloat162*>(lo)[2 * i]     = c;
        reinterpret_cast<__nv_bfloat162*>(lo)[2 * i + 1] = d;
    }
}

__global__ void avg_softmax_kernel(const __nv_bfloat16* __restrict__ xhh,
                                   const __nv_bfloat16* __restrict__ xhl,
                                   const float* __restrict__ embed,
                                   float* __restrict__ ew)
{
    __shared__ float avg_s[DD];
    __shared__ float lg[EE_N];

    const int g = blockIdx.x;
    const int d = threadIdx.x;
    const int b = g >> 7;
    const int n = (g >> 3) & 15;
    const int h = g & 7;

    const long long base = (long long)(b * SS_ + n * SEGLEN) * HID + h * DD + d;
    float s = 0.f;
#pragma unroll 8
    for (int l = 0; l < SEGLEN; l++) {
        long long p = base + (long long)l * HID;
        s += __bfloat162float(xhh[p]) + __bfloat162float(xhl[p]);
    }
    avg_s[d] = s * (1.f / (float)SEGLEN);
    __syncthreads();

    if (d < EE_N) {
        float a = 0.f;
        for (int dd = 0; dd < DD; dd++) a += avg_s[dd] * embed[dd * EE_N + d];
        lg[d] = a;
    }
    __syncthreads();

    if (d == 0) {
        float mx = lg[0];
        for (int e = 1; e < EE_N; e++) mx = fmaxf(mx, lg[e]);
        float ex[EE_N], ssum = 0.f;
        for (int e = 0; e < EE_N; e++) { ex[e] = expf(lg[e] - mx); ssum += ex[e]; }
        float inv = 1.f / ssum;
        for (int e = 0; e < EE_N; e++) ew[g * EE_N + e] = ex[e] * inv;
    }
}

__global__ void mix_kernel(const float* __restrict__ ew,
                           const float* __restrict__ fl1,
                           const float* __restrict__ fl2,
                           __nv_bfloat16* __restrict__ m1h, __nv_bfloat16* __restrict__ m1l,
                           __nv_bfloat16* __restrict__ m2h, __nv_bfloat16* __restrict__ m2l)
{
    __shared__ float w_s[NGROUP * EE_N];
    const int t = threadIdx.x;
    const float* src = blockIdx.y ? fl2 : fl1;
    __nv_bfloat16* dh = blockIdx.y ? m2h : m1h;
    __nv_bfloat16* dl = blockIdx.y ? m2l : m1l;
    const long long p = (long long)blockIdx.x * 128 + t;

    for (int idx = t; idx < NGROUP * EE_N; idx += 128) {
        int g = idx >> 4;
        int n = (g >> 3) & 15;
        int gs = (n > 0) ? (g - HEADS) : g;
        w_s[idx] = ew[gs * EE_N + (idx & 15)];
    }
    float flr[EE_N];
#pragma unroll
    for (int e = 0; e < EE_N; e++) flr[e] = src[(long long)e * (II * DD) + p];
    __syncthreads();

    for (int g = 0; g < NGROUP; g++) {
        float acc = 0.f;
#pragma unroll
        for (int e = 0; e < EE_N; e++) acc = fmaf(w_s[g * EE_N + e], flr[e], acc);
        __nv_bfloat16 h = __float2bfloat16(acc);
        dh[(long long)g * (II * DD) + p] = h;
        dl[(long long)g * (II * DD) + p] = __float2bfloat16(acc - __bfloat162float(h));
    }
}

extern "C" void kernel_launch(void* const* d_in, const int* in_sizes, int n_in,
                              void* d_out, int out_size)
{
    const float* x       = (const float*)d_in[0];
    const float* W_mh    = (const float*)d_in[1];
    const float* b_mh    = (const float*)d_in[2];
    const float* W_merge = (const float*)d_in[3];
    const float* b_merge = (const float*)d_in[4];
    const float* embed   = (const float*)d_in[5];
    const float* fl1     = (const float*)d_in[6];
    const float* fl2     = (const float*)d_in[7];
    float* out = (float*)d_out;

    __nv_bfloat16 *xbh, *xbl, *wmhh, *wmhl, *wmgh, *wmgl, *xhh, *xhl;
    __nv_bfloat16 *m1h, *m1l, *m2h, *m2l, *hh, *hl, *y2h, *y2l;
    float* ew;
    cudaGetSymbolAddress((void**)&xbh, g_xb_hi);   cudaGetSymbolAddress((void**)&xbl, g_xb_lo);
    cudaGetSymbolAddress((void**)&wmhh, g_wmh_hi); cudaGetSymbolAddress((void**)&wmhl, g_wmh_lo);
    cudaGetSymbolAddress((void**)&wmgh, g_wmg_hi); cudaGetSymbolAddress((void**)&wmgl, g_wmg_lo);
    cudaGetSymbolAddress((void**)&xhh, g_xh_hi);   cudaGetSymbolAddress((void**)&xhl, g_xh_lo);
    cudaGetSymbolAddress((void**)&m1h, g_m1_hi);   cudaGetSymbolAddress((void**)&m1l, g_m1_lo);
    cudaGetSymbolAddress((void**)&m2h, g_m2_hi);   cudaGetSymbolAddress((void**)&m2l, g_m2_lo);
    cudaGetSymbolAddress((void**)&hh, g_h_hi);     cudaGetSymbolAddress((void**)&hl, g_h_lo);
    cudaGetSymbolAddress((void**)&y2h, g_y2_hi);   cudaGetSymbolAddress((void**)&y2l, g_y2_lo);
    cudaGetSymbolAddress((void**)&ew, g_ew);

    cudaFuncSetAttribute(mma_gemm, cudaFuncAttributeMaxDynamicSharedMemorySize, SMEM_BYTES);

    // 0) split fp32 inputs into bf16 hi/lo planes
    split_kernel<<<2048, 256>>>((const float4*)x, xbh, xbl, MROWS * HID / 4);
    split_kernel<<<256, 256>>>((const float4*)W_mh, wmhh, wmhl, HID * HID / 4);
    split_kernel<<<256, 256>>>((const float4*)W_merge, wmgh, wmgl, HID * HID / 4);

    // 1) xh = x @ W_mh^T + b_mh -> bf16 hi/lo planes
    mma_gemm<<<dim3(HID / 128, MROWS / 128, 1), 256, SMEM_BYTES>>>(
        xbh, xbl, wmhh, wmhl, xhh, xhl, nullptr, b_mh,
        HID, HID, HID, HID, 0, 0, 0, 0);

    // 2) routing softmax
    avg_softmax_kernel<<<NGROUP, DD>>>(xhh, xhl, embed, ew);

    // 3) causally-shifted expert mixing
    mix_kernel<<<dim3(II * DD / 128, 2), 128>>>(ew, fl1, fl2, m1h, m1l, m2h, m2l);

    // 4) h = relu(X @ m1^T)  batched 512x: M=256,N=512,K=128
    mma_gemm<<<dim3(II / 128, SEGLEN / 128, NGROUP), 256, SMEM_BYTES>>>(
        xhh, xhl, m1h, m1l, hh, hl, nullptr, nullptr,
        DD, DD, DD, II,
        (long long)SEGLEN * DD, (long long)II * DD, (long long)SEGLEN * II, 1);

    // 5) y2 = h @ m2^T  batched 512x: M=256,N=128,K=512
    mma_gemm<<<dim3(DD / 128, SEGLEN / 128, NGROUP), 256, SMEM_BYTES>>>(
        hh, hl, m2h, m2l, y2h, y2l, nullptr, nullptr,
        II, II, II, DD,
        (long long)SEGLEN * II, (long long)DD * II, (long long)SEGLEN * DD, 0);

    // 6) out = y2 @ W_merge^T + b_merge (fp32 out)
    mma_gemm<<<dim3(HID / 128, MROWS / 128, 1), 256, SMEM_BYTES>>>(
        y2h, y2l, wmgh, wmgl, nullptr, nullptr, out, b_merge,
        HID, HID, HID, HID, 0, 0, 0, 0);
}